// round 10
// baseline (speedup 1.0000x reference)
#include <cuda_runtime.h>
#include <math.h>
#include <stdint.h>

// Problem constants (per reference setup_inputs)
#define BB 8
#define NN 4096
#define CC 256
#define HN 8
#define DH 32
#define NPART 32   // kv partials per batch

// per-block kv partials [b][i][h][e][d] and reduced kv [b][h][e][d]
__device__ float g_kvp[BB * NPART * HN * DH * DH];
__device__ float g_kv[BB * HN * DH * DH];

// conv weight + bias in constant bank
__constant__ float c_W[DH * DH];
__constant__ float c_b[DH];

// ---------------- helpers ----------------

__device__ __forceinline__ float2 ffma2(float2 a, float2 b, float2 c) {
    union U { float2 f; unsigned long long u; };
    U A, B_, C_, D;
    A.f = a; B_.f = b; C_.f = c;
    asm("fma.rn.f32x2 %0, %1, %2, %3;" : "=l"(D.u) : "l"(A.u), "l"(B_.u), "l"(C_.u));
    return D.f;
}

__device__ __forceinline__ float leaky1(float x) { return fmaxf(x, 0.1f * x); }

__device__ __forceinline__ float4 prep4(float4 a, float4 p, float4 rs) {
    float4 r;
    r.x = leaky1(a.x + p.x) * rs.x;
    r.y = leaky1(a.y + p.y) * rs.y;
    r.z = leaky1(a.z + p.z) * rs.z;
    r.w = leaky1(a.w + p.w) * rs.w;
    return r;
}

__device__ __forceinline__ float dot4(float4 a, float4 b) {
    return a.x * b.x + a.y * b.y + a.z * b.z + a.w * b.w;
}

__device__ __forceinline__ float4 cube4(float4 a) {
    float4 r;
    r.x = a.x * a.x * a.x; r.y = a.y * a.y * a.y;
    r.z = a.z * a.z * a.z; r.w = a.w * a.w * a.w;
    return r;
}

__device__ __forceinline__ float4 mul4s(float4 a, float s) {
    float4 r; r.x = a.x * s; r.y = a.y * s; r.z = a.z * s; r.w = a.w * s; return r;
}

__device__ __forceinline__ float4 rsoft4(const float* scale, int i) {
    float4 s = reinterpret_cast<const float4*>(scale)[i];
    float4 r;
    r.x = 1.0f / log1pf(expf(s.x));
    r.y = 1.0f / log1pf(expf(s.y));
    r.z = 1.0f / log1pf(expf(s.z));
    r.w = 1.0f / log1pf(expf(s.w));
    return r;
}

__device__ __forceinline__ void cp_async16(uint32_t saddr, const void* g) {
    asm volatile("cp.async.cg.shared.global [%0], [%1], 16;" :: "r"(saddr), "l"(g));
}
#define CP_COMMIT() asm volatile("cp.async.commit_group;")
#define CP_WAIT0()  asm volatile("cp.async.wait_group 0;")
#define CP_WAIT1()  asm volatile("cp.async.wait_group 1;")

__device__ __forceinline__ uint32_t s2u(const void* p) {
    return (uint32_t)__cvta_generic_to_shared(p);
}

// MUFU-based sqrt(s2/s6) = rsqrt(s6 * rcp(s2))
__device__ __forceinline__ float focus_factor(float s2, float s6, float extra) {
    return (s6 > 0.f) ? __frsqrt_rn(s6 * __frcp_rn(s2)) * extra : 0.f;
}

// feature transform of one row held warp-wide in registers; writes focused row to smem
__device__ __forceinline__ void transform_store(
    float4 a0, float4 a1, float4 p0, float4 p1,
    float4 rs0, float4 rs1, float* qrow, int lane, float extra)
{
    float4 t0 = prep4(a0, p0, rs0);
    float4 t1 = prep4(a1, p1, rs1);
    float s2 = dot4(t0, t0) + dot4(t1, t1);
    float4 u0 = cube4(t0), u1 = cube4(t1);
    float s6 = dot4(u0, u0) + dot4(u1, u1);
#pragma unroll
    for (int m = 16; m; m >>= 1) {
        s2 += __shfl_xor_sync(0xffffffffu, s2, m);
        s6 += __shfl_xor_sync(0xffffffffu, s6, m);
    }
    const float f = focus_factor(s2, s6, extra);
    reinterpret_cast<float4*>(qrow)[lane]      = mul4s(u0, f);
    reinterpret_cast<float4*>(qrow)[32 + lane] = mul4s(u1, f);
}

// ---------------- kernel 1: fused k-feature + kv partial accumulation ----------------
// grid (32, 8), 256 threads (8 warps, warp = head). 128 rows/block, 16 groups of 8.
// 3-buffer cp.async ring (2 sets in flight). ONE barrier per group.
// RACE-SAFE STAGING: warp w copies k-row w and pe-row w ITSELF (the rows it
// transforms), so a converged wait_group makes them visible warp-wide with no
// block barrier. v is tid-strided; its consumers run post-__syncthreads, which
// orders every thread's completed wait of the same set.

#define KV_GRP 2048  // floats per 8-row group buffer
#define KV_SMEM_FLOATS (9 * KV_GRP + 2 * KV_GRP)   // kb[3] pb[3] vb[3] + kf[2] = 88KB
#define KV_SMEM_BYTES (KV_SMEM_FLOATS * 4)

__device__ __forceinline__ void kv_issue_set(
    float* kb, float* pb, float* vb,
    const float* k, const float* v, const float* pe2,
    int b, int row0, int w, int lane, int tid)
{
    // warp-owned k/pe row w (consumed by this same warp after converged wait)
    const size_t krow = ((size_t)b * NN + row0 + w) * CC;
    const size_t prow = (size_t)(row0 + w) * CC;
    cp_async16(s2u(kb + w * 256 + lane * 4),       k   + krow + lane * 4);
    cp_async16(s2u(kb + w * 256 + 128 + lane * 4), k   + krow + 128 + lane * 4);
    cp_async16(s2u(pb + w * 256 + lane * 4),       pe2 + prow + lane * 4);
    cp_async16(s2u(pb + w * 256 + 128 + lane * 4), pe2 + prow + 128 + lane * 4);
    // v: all 8 rows cooperatively (consumed only after a block barrier)
#pragma unroll
    for (int i = 0; i < 2; i++) {
        int idx = i * 256 + tid;
        int r = idx >> 6, c = (idx & 63) * 4;
        cp_async16(s2u(vb + r * 256 + c), v + ((size_t)b * NN + row0 + r) * CC + c);
    }
    CP_COMMIT();
}

__global__ void __launch_bounds__(256, 2) kv_kernel(
    const float* __restrict__ k, const float* __restrict__ v,
    const float* __restrict__ pe2, const float* __restrict__ scale)
{
    extern __shared__ float smv[];
    float* kb[3] = { smv,              smv + KV_GRP,     smv + 2 * KV_GRP };
    float* pb[3] = { smv + 3 * KV_GRP, smv + 4 * KV_GRP, smv + 5 * KV_GRP };
    float* vb[3] = { smv + 6 * KV_GRP, smv + 7 * KV_GRP, smv + 8 * KV_GRP };
    float* kf[2] = { smv + 9 * KV_GRP, smv + 10 * KV_GRP };

    const int tid = threadIdx.x;
    const int w = tid >> 5;
    const int lane = tid & 31;
    const int b = blockIdx.y;
    const int n0 = blockIdx.x * 128;

    const float4 rs0 = rsoft4(scale, lane);
    const float4 rs1 = rsoft4(scale, 32 + lane);

    float2 acc[16];
#pragma unroll
    for (int j = 0; j < 16; j++) acc[j] = make_float2(0.f, 0.f);

    // prologue: two sets in flight; transform group 0 (self-warp rows); publish
    kv_issue_set(kb[0], pb[0], vb[0], k, v, pe2, b, n0,     w, lane, tid);
    kv_issue_set(kb[1], pb[1], vb[1], k, v, pe2, b, n0 + 8, w, lane, tid);
    CP_WAIT1();   // set_0 complete (per-lane; converged warp => row w visible)
    {
        const float4* kr = reinterpret_cast<const float4*>(kb[0] + w * 256);
        const float4* pr = reinterpret_cast<const float4*>(pb[0] + w * 256);
        float4 a0 = kr[lane], a1 = kr[32 + lane];
        float4 p0 = pr[lane], p1 = pr[32 + lane];
        transform_store(a0, a1, p0, p1, rs0, rs1, kf[0] + w * 256, lane, 1.0f);
    }
    __syncthreads();   // kf_0 + v_0 visible block-wide

#pragma unroll 1
    for (int g = 0; g < 16; g++) {
        const int buf = g % 3;
        const int kbuf = g & 1;

        // keep the ring full: set_{g+2}
        if (g < 14)
            kv_issue_set(kb[(g + 2) % 3], pb[(g + 2) % 3], vb[(g + 2) % 3],
                         k, v, pe2, b, n0 + (g + 2) * 8, w, lane, tid);

        // transform of group g+1 (self-warp k/pe rows), interleavable with the
        // accumulate below in the same issue window.
        float4 u0, u1; float s2 = 0.f, s6 = 0.f;
        if (g < 15) {
            if (g < 14) { CP_WAIT1(); } else { CP_WAIT0(); }   // set_{g+1} complete
            const int nb = (g + 1) % 3;
            const float4* kr = reinterpret_cast<const float4*>(kb[nb] + w * 256);
            const float4* pr = reinterpret_cast<const float4*>(pb[nb] + w * 256);
            float4 a0 = kr[lane], a1 = kr[32 + lane];
            float4 p0 = pr[lane], p1 = pr[32 + lane];
            float4 t0 = prep4(a0, p0, rs0);
            float4 t1 = prep4(a1, p1, rs1);
            s2 = dot4(t0, t0) + dot4(t1, t1);
            u0 = cube4(t0); u1 = cube4(t1);
            s6 = dot4(u0, u0) + dot4(u1, u1);
#pragma unroll
            for (int m = 16; m; m >>= 1) {
                s2 += __shfl_xor_sync(0xffffffffu, s2, m);
                s6 += __shfl_xor_sync(0xffffffffu, s6, m);
            }
        }

        // accumulate group g: thread owns d=lane for head w, all 32 e
        // (vb[buf] and kf[kbuf] both sealed by the previous __syncthreads)
#pragma unroll
        for (int r = 0; r < 8; r++) {
            const float kd = kf[kbuf][r * 256 + w * 32 + lane];
            const float2 k2 = make_float2(kd, kd);
            const float4* vp = reinterpret_cast<const float4*>(vb[buf] + r * 256 + w * 32);
#pragma unroll
            for (int j = 0; j < 8; j++) {
                float4 vv = vp[j];
                acc[2 * j]     = ffma2(k2, make_float2(vv.x, vv.y), acc[2 * j]);
                acc[2 * j + 1] = ffma2(k2, make_float2(vv.z, vv.w), acc[2 * j + 1]);
            }
        }

        // finish + publish transform of g+1
        if (g < 15) {
            const float f = focus_factor(s2, s6, 1.0f);
            float* qrow = kf[kbuf ^ 1] + w * 256;
            reinterpret_cast<float4*>(qrow)[lane]      = mul4s(u0, f);
            reinterpret_cast<float4*>(qrow)[32 + lane] = mul4s(u1, f);
        }
        __syncthreads();
    }

    // plain coalesced store of this block's partial: [b][i][h][e][d]
    float* base = g_kvp + (((size_t)b * NPART + blockIdx.x) * HN + w) * (DH * DH);
#pragma unroll
    for (int j = 0; j < 16; j++) {
        base[(2 * j) * DH + lane]     = acc[j].x;
        base[(2 * j + 1) * DH + lane] = acc[j].y;
    }
}

// ---------------- kernel 1b: reduce the 32 partials ----------------

__global__ void __launch_bounds__(256) reduce_kernel() {
    const int o = blockIdx.x * 256 + threadIdx.x;       // float4 index, 16384 total
    const int b = o >> 11;                              // 2048 float4 per batch
    const int r = o & 2047;
    const float4* src = reinterpret_cast<const float4*>(g_kvp) + (size_t)b * (NPART * 2048) + r;
    float4 s = make_float4(0.f, 0.f, 0.f, 0.f);
#pragma unroll
    for (int i = 0; i < NPART; i++) {
        float4 t = src[(size_t)i * 2048];
        s.x += t.x; s.y += t.y; s.z += t.z; s.w += t.w;
    }
    reinterpret_cast<float4*>(g_kv)[o] = s;
}

// ---------------- kernel 2: q-feature + x = qf@kv + leaky(v@W^T + b) ----------------
// (unchanged from the 94.2us baseline)

#define ROWPAD 260
#define SMEM_FLOATS (2 * 32 * ROWPAD + HN * DH * DH)
#define SMEM_BYTES (SMEM_FLOATS * 4)

__global__ void __launch_bounds__(256, 2) out_kernel(
    const float* __restrict__ q, const float* __restrict__ v,
    const float* __restrict__ pe1, const float* __restrict__ scale,
    float* __restrict__ out)
{
    extern __shared__ float sm[];
    float* sqf = sm;                       // 32*260
    float* svs = sm + 32 * ROWPAD;         // 32*260
    float* skv = sm + 2 * 32 * ROWPAD;     // 8192  [h][e][d]

    const int tid = threadIdx.x;
    const int w = tid >> 5;
    const int lane = tid & 31;
    const int b = blockIdx.y;

    {
        const float4* kvg = reinterpret_cast<const float4*>(g_kv + (size_t)b * HN * DH * DH);
        float4* skv4 = reinterpret_cast<float4*>(skv);
#pragma unroll
        for (int i = 0; i < 8; i++) skv4[i * 256 + tid] = kvg[i * 256 + tid];
    }

    const float4 rs0 = rsoft4(scale, lane);
    const float4 rs1 = rsoft4(scale, 32 + lane);
    const float invN = 1.0f / (float)NN;

    for (int it = 0; it < 4; it++) {
        const int n0 = (blockIdx.x * 4 + it) * 32;

        __syncthreads();

#pragma unroll
        for (int i = 0; i < 4; i++) {
            const int rl = w * 4 + i;
            const int row = n0 + rl;
            const float4* qg = reinterpret_cast<const float4*>(q + ((size_t)b * NN + row) * CC);
            const float4* vg = reinterpret_cast<const float4*>(v + ((size_t)b * NN + row) * CC);
            const float4* pg = reinterpret_cast<const float4*>(pe1 + (size_t)row * CC);

            float4 a0 = qg[lane], a1 = qg[32 + lane];
            float4 v0 = vg[lane], v1 = vg[32 + lane];
            float4 p0 = pg[lane], p1 = pg[32 + lane];

            transform_store(a0, a1, p0, p1, rs0, rs1, &sqf[rl * ROWPAD], lane, invN);
            float* vrow = svs + rl * ROWPAD;
            *reinterpret_cast<float4*>(vrow + lane * 4)       = v0;
            *reinterpret_cast<float4*>(vrow + 128 + lane * 4) = v1;
        }
        __syncthreads();

        float2 q2[16], v2[16];
        {
            const float4* qp = reinterpret_cast<const float4*>(sqf + lane * ROWPAD + w * DH);
            const float4* vp = reinterpret_cast<const float4*>(svs + lane * ROWPAD + w * DH);
#pragma unroll
            for (int j = 0; j < 8; j++) {
                float4 t = qp[j];
                q2[2 * j]     = make_float2(t.x, t.y);
                q2[2 * j + 1] = make_float2(t.z, t.w);
                float4 s = vp[j];
                v2[2 * j]     = make_float2(s.x, s.y);
                v2[2 * j + 1] = make_float2(s.z, s.w);
            }
        }

        const int n = n0 + lane;
        float* outb = out + ((size_t)b * CC + w * DH) * NN + n;

#pragma unroll 4
        for (int e = 0; e < DH; e++) {
            const float4* kp = reinterpret_cast<const float4*>(skv + w * (DH * DH) + e * DH);
            const float4* wp = reinterpret_cast<const float4*>(c_W + e * DH);
            float2 ax0 = make_float2(0.f, 0.f), ax1 = make_float2(0.f, 0.f);
            float2 ac0 = make_float2(0.f, 0.f), ac1 = make_float2(0.f, 0.f);
#pragma unroll
            for (int j = 0; j < 4; j++) {
                float4 kd0 = kp[2 * j], kd1 = kp[2 * j + 1];
                float4 wd0 = wp[2 * j], wd1 = wp[2 * j + 1];
                ax0 = ffma2(q2[4 * j],     make_float2(kd0.x, kd0.y), ax0);
                ax1 = ffma2(q2[4 * j + 1], make_float2(kd0.z, kd0.w), ax1);
                ax0 = ffma2(q2[4 * j + 2], make_float2(kd1.x, kd1.y), ax0);
                ax1 = ffma2(q2[4 * j + 3], make_float2(kd1.z, kd1.w), ax1);
                ac0 = ffma2(v2[4 * j],     make_float2(wd0.x, wd0.y), ac0);
                ac1 = ffma2(v2[4 * j + 1], make_float2(wd0.z, wd0.w), ac1);
                ac0 = ffma2(v2[4 * j + 2], make_float2(wd1.x, wd1.y), ac0);
                ac1 = ffma2(v2[4 * j + 3], make_float2(wd1.z, wd1.w), ac1);
            }
            float xv = (ax0.x + ax0.y) + (ax1.x + ax1.y);
            float cv = leaky1((ac0.x + ac0.y) + (ac1.x + ac1.y) + c_b[e]);
            outb[(size_t)e * NN] = xv + cv;
        }
    }
}

// ---------------- launch ----------------

extern "C" void kernel_launch(void* const* d_in, const int* in_sizes, int n_in,
                              void* d_out, int out_size)
{
    (void)in_sizes; (void)n_in; (void)out_size;
    const float* q     = (const float*)d_in[0];
    const float* k     = (const float*)d_in[1];
    const float* v     = (const float*)d_in[2];
    const float* pe1   = (const float*)d_in[3];
    const float* pe2   = (const float*)d_in[4];
    const float* scale = (const float*)d_in[5];
    const float* wconv = (const float*)d_in[6];
    const float* bconv = (const float*)d_in[7];
    float* out = (float*)d_out;

    cudaFuncSetAttribute(kv_kernel, cudaFuncAttributeMaxDynamicSharedMemorySize, KV_SMEM_BYTES);
    cudaFuncSetAttribute(out_kernel, cudaFuncAttributeMaxDynamicSharedMemorySize, SMEM_BYTES);

    cudaMemcpyToSymbolAsync(c_W, wconv, DH * DH * sizeof(float), 0, cudaMemcpyDeviceToDevice);
    cudaMemcpyToSymbolAsync(c_b, bconv, DH * sizeof(float), 0, cudaMemcpyDeviceToDevice);

    kv_kernel<<<dim3(NPART, BB), 256, KV_SMEM_BYTES>>>(k, v, pe2, scale);
    reduce_kernel<<<64, 256>>>();
    out_kernel<<<dim3(NN / 128, BB), 256, SMEM_BYTES>>>(q, v, pe1, scale, out);
}

// round 11
// speedup vs baseline: 1.2409x; 1.2409x over previous
#include <cuda_runtime.h>
#include <math.h>
#include <stdint.h>

// Problem constants (per reference setup_inputs)
#define BB 8
#define NN 4096
#define CC 256
#define HN 8
#define DH 32
#define NPART 32   // kv partials per batch

// per-block kv partials [b][i][h][e][d] and reduced kv [b][h][e][d]
__device__ float g_kvp[BB * NPART * HN * DH * DH];
__device__ float g_kv[BB * HN * DH * DH];

// conv weight + bias in constant bank
__constant__ float c_W[DH * DH];
__constant__ float c_b[DH];

// ---------------- helpers ----------------

__device__ __forceinline__ float2 ffma2(float2 a, float2 b, float2 c) {
    union U { float2 f; unsigned long long u; };
    U A, B_, C_, D;
    A.f = a; B_.f = b; C_.f = c;
    asm("fma.rn.f32x2 %0, %1, %2, %3;" : "=l"(D.u) : "l"(A.u), "l"(B_.u), "l"(C_.u));
    return D.f;
}

__device__ __forceinline__ float leaky1(float x) { return fmaxf(x, 0.1f * x); }

__device__ __forceinline__ float4 prep4(float4 a, float4 p, float4 rs) {
    float4 r;
    r.x = leaky1(a.x + p.x) * rs.x;
    r.y = leaky1(a.y + p.y) * rs.y;
    r.z = leaky1(a.z + p.z) * rs.z;
    r.w = leaky1(a.w + p.w) * rs.w;
    return r;
}

__device__ __forceinline__ float dot4(float4 a, float4 b) {
    return a.x * b.x + a.y * b.y + a.z * b.z + a.w * b.w;
}

__device__ __forceinline__ float4 cube4(float4 a) {
    float4 r;
    r.x = a.x * a.x * a.x; r.y = a.y * a.y * a.y;
    r.z = a.z * a.z * a.z; r.w = a.w * a.w * a.w;
    return r;
}

__device__ __forceinline__ float4 mul4s(float4 a, float s) {
    float4 r; r.x = a.x * s; r.y = a.y * s; r.z = a.z * s; r.w = a.w * s; return r;
}

__device__ __forceinline__ float4 rsoft4(const float* scale, int i) {
    float4 s = reinterpret_cast<const float4*>(scale)[i];
    float4 r;
    r.x = 1.0f / log1pf(expf(s.x));
    r.y = 1.0f / log1pf(expf(s.y));
    r.z = 1.0f / log1pf(expf(s.z));
    r.w = 1.0f / log1pf(expf(s.w));
    return r;
}

__device__ __forceinline__ void cp_async16(uint32_t saddr, const void* g) {
    asm volatile("cp.async.cg.shared.global [%0], [%1], 16;" :: "r"(saddr), "l"(g));
}
#define CP_COMMIT() asm volatile("cp.async.commit_group;")
#define CP_WAIT0()  asm volatile("cp.async.wait_group 0;")

__device__ __forceinline__ uint32_t s2u(const void* p) {
    return (uint32_t)__cvta_generic_to_shared(p);
}

// MUFU-based sqrt(s2/s6) = rsqrt(s6 * rcp(s2))
__device__ __forceinline__ float focus_factor(float s2, float s6, float extra) {
    return (s6 > 0.f) ? __frsqrt_rn(s6 * __frcp_rn(s2)) * extra : 0.f;
}

// feature transform of one row held warp-wide in registers; writes focused row to smem
__device__ __forceinline__ void transform_store(
    float4 a0, float4 a1, float4 p0, float4 p1,
    float4 rs0, float4 rs1, float* qrow, int lane, float extra)
{
    float4 t0 = prep4(a0, p0, rs0);
    float4 t1 = prep4(a1, p1, rs1);
    float s2 = dot4(t0, t0) + dot4(t1, t1);
    float4 u0 = cube4(t0), u1 = cube4(t1);
    float s6 = dot4(u0, u0) + dot4(u1, u1);
#pragma unroll
    for (int m = 16; m; m >>= 1) {
        s2 += __shfl_xor_sync(0xffffffffu, s2, m);
        s6 += __shfl_xor_sync(0xffffffffu, s6, m);
    }
    const float f = focus_factor(s2, s6, extra);
    reinterpret_cast<float4*>(qrow)[lane]      = mul4s(u0, f);
    reinterpret_cast<float4*>(qrow)[32 + lane] = mul4s(u1, f);
}

// two independent row transforms with interleaved shfl chains (shared latency window)
__device__ __forceinline__ void transform2_store(
    float4 Aa0, float4 Aa1, float4 Ap0, float4 Ap1, float* qrowA,
    float4 Ba0, float4 Ba1, float4 Bp0, float4 Bp1, float* qrowB,
    float4 rs0, float4 rs1, int lane, float extra)
{
    float4 tA0 = prep4(Aa0, Ap0, rs0), tA1 = prep4(Aa1, Ap1, rs1);
    float4 tB0 = prep4(Ba0, Bp0, rs0), tB1 = prep4(Ba1, Bp1, rs1);
    float s2a = dot4(tA0, tA0) + dot4(tA1, tA1);
    float s2b = dot4(tB0, tB0) + dot4(tB1, tB1);
    float4 uA0 = cube4(tA0), uA1 = cube4(tA1);
    float4 uB0 = cube4(tB0), uB1 = cube4(tB1);
    float s6a = dot4(uA0, uA0) + dot4(uA1, uA1);
    float s6b = dot4(uB0, uB0) + dot4(uB1, uB1);
#pragma unroll
    for (int m = 16; m; m >>= 1) {
        s2a += __shfl_xor_sync(0xffffffffu, s2a, m);
        s6a += __shfl_xor_sync(0xffffffffu, s6a, m);
        s2b += __shfl_xor_sync(0xffffffffu, s2b, m);
        s6b += __shfl_xor_sync(0xffffffffu, s6b, m);
    }
    const float fa = focus_factor(s2a, s6a, extra);
    const float fb = focus_factor(s2b, s6b, extra);
    reinterpret_cast<float4*>(qrowA)[lane]      = mul4s(uA0, fa);
    reinterpret_cast<float4*>(qrowA)[32 + lane] = mul4s(uA1, fa);
    reinterpret_cast<float4*>(qrowB)[lane]      = mul4s(uB0, fb);
    reinterpret_cast<float4*>(qrowB)[32 + lane] = mul4s(uB1, fb);
}

// ---------------- kernel 1: fused k-feature + kv partial accumulation ----------------
// EXACT round-8 structure (measured 35.5us): grid (32,8), 256 threads, warp = head.
// 128 rows per block as 16 groups of 8. v staged via cp.async, k+pe
// register-prefetched under the accumulate. One barrier per group.

__global__ void __launch_bounds__(256, 2) kv_kernel(
    const float* __restrict__ k, const float* __restrict__ v,
    const float* __restrict__ pe2, const float* __restrict__ scale)
{
    __shared__ float ks[2][8 * 256];
    __shared__ float vsm[2][8 * 256];

    const int tid = threadIdx.x;
    const int w = tid >> 5;
    const int lane = tid & 31;
    const int b = blockIdx.y;
    const int n0 = blockIdx.x * 128;

    const float4 rs0 = rsoft4(scale, lane);
    const float4 rs1 = rsoft4(scale, 32 + lane);

    float2 acc[16];
#pragma unroll
    for (int j = 0; j < 16; j++) acc[j] = make_float2(0.f, 0.f);

#pragma unroll
    for (int i = 0; i < 2; i++) {
        int idx = i * 256 + tid;
        int r = idx >> 6, c = idx & 63;
        cp_async16(s2u(&vsm[0][r * 256 + c * 4]),
                   v + ((size_t)b * NN + n0 + r) * CC + c * 4);
    }
    CP_COMMIT();

    float4 ka0, ka1, pa0, pa1;
    {
        const int row = n0 + w;
        const float4* kg = reinterpret_cast<const float4*>(k + ((size_t)b * NN + row) * CC);
        const float4* pg = reinterpret_cast<const float4*>(pe2 + (size_t)row * CC);
        ka0 = kg[lane]; ka1 = kg[32 + lane];
        pa0 = pg[lane]; pa1 = pg[32 + lane];
    }

    for (int g = 0; g < 16; g++) {
        const int buf = g & 1;

        transform_store(ka0, ka1, pa0, pa1, rs0, rs1, &ks[buf][w * 256], lane, 1.0f);
        CP_WAIT0();
        __syncthreads();

        if (g < 15) {
            const int gn = g + 1;
#pragma unroll
            for (int i = 0; i < 2; i++) {
                int idx = i * 256 + tid;
                int r = idx >> 6, c = idx & 63;
                cp_async16(s2u(&vsm[buf ^ 1][r * 256 + c * 4]),
                           v + ((size_t)b * NN + n0 + gn * 8 + r) * CC + c * 4);
            }
            CP_COMMIT();
            const int row = n0 + gn * 8 + w;
            const float4* kg = reinterpret_cast<const float4*>(k + ((size_t)b * NN + row) * CC);
            const float4* pg = reinterpret_cast<const float4*>(pe2 + (size_t)row * CC);
            ka0 = kg[lane]; ka1 = kg[32 + lane];
            pa0 = pg[lane]; pa1 = pg[32 + lane];
        }

#pragma unroll
        for (int r = 0; r < 8; r++) {
            const float kd = ks[buf][r * 256 + w * 32 + lane];
            const float2 k2 = make_float2(kd, kd);
            const float4* vp = reinterpret_cast<const float4*>(&vsm[buf][r * 256 + w * 32]);
#pragma unroll
            for (int j = 0; j < 8; j++) {
                float4 vv = vp[j];
                acc[2 * j]     = ffma2(k2, make_float2(vv.x, vv.y), acc[2 * j]);
                acc[2 * j + 1] = ffma2(k2, make_float2(vv.z, vv.w), acc[2 * j + 1]);
            }
        }
    }

    float* base = g_kvp + (((size_t)b * NPART + blockIdx.x) * HN + w) * (DH * DH);
#pragma unroll
    for (int j = 0; j < 16; j++) {
        base[(2 * j) * DH + lane]     = acc[j].x;
        base[(2 * j + 1) * DH + lane] = acc[j].y;
    }
}

// ---------------- kernel 1b: reduce the 32 partials ----------------

__global__ void __launch_bounds__(256) reduce_kernel() {
    const int o = blockIdx.x * 256 + threadIdx.x;       // float4 index, 16384 total
    const int b = o >> 11;
    const int r = o & 2047;
    const float4* src = reinterpret_cast<const float4*>(g_kvp) + (size_t)b * (NPART * 2048) + r;
    float4 s = make_float4(0.f, 0.f, 0.f, 0.f);
#pragma unroll
    for (int i = 0; i < NPART; i++) {
        float4 t = src[(size_t)i * 2048];
        s.x += t.x; s.y += t.y; s.z += t.z; s.w += t.w;
    }
    reinterpret_cast<float4*>(g_kv)[o] = s;
}

// ---------------- kernel 2: q-feature + x = qf@kv + leaky(v@W^T + b) ----------------
// grid (64, 8) = 512 blocks x 2 tiles (better wave balance than 256x4), 256
// threads (warp = head), 2 CTAs/SM. Phase-1 uses paired transforms with
// interleaved shfl chains. W + bias from the constant bank.

#define OUT_TILES 2
#define ROWPAD 260
#define SMEM_FLOATS (2 * 32 * ROWPAD + HN * DH * DH)
#define SMEM_BYTES (SMEM_FLOATS * 4)

__global__ void __launch_bounds__(256, 2) out_kernel(
    const float* __restrict__ q, const float* __restrict__ v,
    const float* __restrict__ pe1, const float* __restrict__ scale,
    float* __restrict__ out)
{
    extern __shared__ float sm[];
    float* sqf = sm;                       // 32*260
    float* svs = sm + 32 * ROWPAD;         // 32*260
    float* skv = sm + 2 * 32 * ROWPAD;     // 8192  [h][e][d]

    const int tid = threadIdx.x;
    const int w = tid >> 5;
    const int lane = tid & 31;
    const int b = blockIdx.y;

    {
        const float4* kvg = reinterpret_cast<const float4*>(g_kv + (size_t)b * HN * DH * DH);
        float4* skv4 = reinterpret_cast<float4*>(skv);
#pragma unroll
        for (int i = 0; i < 8; i++) skv4[i * 256 + tid] = kvg[i * 256 + tid];
    }

    const float4 rs0 = rsoft4(scale, lane);
    const float4 rs1 = rsoft4(scale, 32 + lane);
    const float invN = 1.0f / (float)NN;

    for (int it = 0; it < OUT_TILES; it++) {
        const int n0 = (blockIdx.x * OUT_TILES + it) * 32;

        __syncthreads();   // previous tile's readers done before rewriting smem

        // phase 1: q features + v staging; 2 row-pairs per warp, chains interleaved
#pragma unroll
        for (int pr = 0; pr < 2; pr++) {
            const int rlA = w * 4 + 2 * pr;
            const int rlB = rlA + 1;
            const int rowA = n0 + rlA, rowB = n0 + rlB;
            const float4* qgA = reinterpret_cast<const float4*>(q + ((size_t)b * NN + rowA) * CC);
            const float4* qgB = reinterpret_cast<const float4*>(q + ((size_t)b * NN + rowB) * CC);
            const float4* vgA = reinterpret_cast<const float4*>(v + ((size_t)b * NN + rowA) * CC);
            const float4* vgB = reinterpret_cast<const float4*>(v + ((size_t)b * NN + rowB) * CC);
            const float4* pgA = reinterpret_cast<const float4*>(pe1 + (size_t)rowA * CC);
            const float4* pgB = reinterpret_cast<const float4*>(pe1 + (size_t)rowB * CC);

            float4 Aa0 = qgA[lane], Aa1 = qgA[32 + lane];
            float4 Ba0 = qgB[lane], Ba1 = qgB[32 + lane];
            float4 Av0 = vgA[lane], Av1 = vgA[32 + lane];
            float4 Bv0 = vgB[lane], Bv1 = vgB[32 + lane];
            float4 Ap0 = pgA[lane], Ap1 = pgA[32 + lane];
            float4 Bp0 = pgB[lane], Bp1 = pgB[32 + lane];

            transform2_store(Aa0, Aa1, Ap0, Ap1, sqf + rlA * ROWPAD,
                             Ba0, Ba1, Bp0, Bp1, sqf + rlB * ROWPAD,
                             rs0, rs1, lane, invN);

            float* vrA = svs + rlA * ROWPAD;
            float* vrB = svs + rlB * ROWPAD;
            *reinterpret_cast<float4*>(vrA + lane * 4)       = Av0;
            *reinterpret_cast<float4*>(vrA + 128 + lane * 4) = Av1;
            *reinterpret_cast<float4*>(vrB + lane * 4)       = Bv0;
            *reinterpret_cast<float4*>(vrB + 128 + lane * 4) = Bv1;
        }
        __syncthreads();

        // phase 2: per-lane row (n = n0+lane), per-warp head (h = w)
        float2 q2[16], v2[16];
        {
            const float4* qp = reinterpret_cast<const float4*>(sqf + lane * ROWPAD + w * DH);
            const float4* vp = reinterpret_cast<const float4*>(svs + lane * ROWPAD + w * DH);
#pragma unroll
            for (int j = 0; j < 8; j++) {
                float4 t = qp[j];
                q2[2 * j]     = make_float2(t.x, t.y);
                q2[2 * j + 1] = make_float2(t.z, t.w);
                float4 s = vp[j];
                v2[2 * j]     = make_float2(s.x, s.y);
                v2[2 * j + 1] = make_float2(s.z, s.w);
            }
        }

        const int n = n0 + lane;
        float* outb = out + ((size_t)b * CC + w * DH) * NN + n;

#pragma unroll 4
        for (int e = 0; e < DH; e++) {
            const float4* kp = reinterpret_cast<const float4*>(skv + w * (DH * DH) + e * DH);
            const float4* wp = reinterpret_cast<const float4*>(c_W + e * DH);
            float2 ax0 = make_float2(0.f, 0.f), ax1 = make_float2(0.f, 0.f);
            float2 ac0 = make_float2(0.f, 0.f), ac1 = make_float2(0.f, 0.f);
#pragma unroll
            for (int j = 0; j < 4; j++) {
                float4 kd0 = kp[2 * j], kd1 = kp[2 * j + 1];
                float4 wd0 = wp[2 * j], wd1 = wp[2 * j + 1];
                ax0 = ffma2(q2[4 * j],     make_float2(kd0.x, kd0.y), ax0);
                ax1 = ffma2(q2[4 * j + 1], make_float2(kd0.z, kd0.w), ax1);
                ax0 = ffma2(q2[4 * j + 2], make_float2(kd1.x, kd1.y), ax0);
                ax1 = ffma2(q2[4 * j + 3], make_float2(kd1.z, kd1.w), ax1);
                ac0 = ffma2(v2[4 * j],     make_float2(wd0.x, wd0.y), ac0);
                ac1 = ffma2(v2[4 * j + 1], make_float2(wd0.z, wd0.w), ac1);
                ac0 = ffma2(v2[4 * j + 2], make_float2(wd1.x, wd1.y), ac0);
                ac1 = ffma2(v2[4 * j + 3], make_float2(wd1.z, wd1.w), ac1);
            }
            float xv = (ax0.x + ax0.y) + (ax1.x + ax1.y);
            float cv = leaky1((ac0.x + ac0.y) + (ac1.x + ac1.y) + c_b[e]);
            outb[(size_t)e * NN] = xv + cv;
        }
    }
}

// ---------------- launch ----------------

extern "C" void kernel_launch(void* const* d_in, const int* in_sizes, int n_in,
                              void* d_out, int out_size)
{
    (void)in_sizes; (void)n_in; (void)out_size;
    const float* q     = (const float*)d_in[0];
    const float* k     = (const float*)d_in[1];
    const float* v     = (const float*)d_in[2];
    const float* pe1   = (const float*)d_in[3];
    const float* pe2   = (const float*)d_in[4];
    const float* scale = (const float*)d_in[5];
    const float* wconv = (const float*)d_in[6];
    const float* bconv = (const float*)d_in[7];
    float* out = (float*)d_out;

    cudaFuncSetAttribute(out_kernel, cudaFuncAttributeMaxDynamicSharedMemorySize, SMEM_BYTES);

    cudaMemcpyToSymbolAsync(c_W, wconv, DH * DH * sizeof(float), 0, cudaMemcpyDeviceToDevice);
    cudaMemcpyToSymbolAsync(c_b, bconv, DH * sizeof(float), 0, cudaMemcpyDeviceToDevice);

    kv_kernel<<<dim3(NPART, BB), 256>>>(k, v, pe2, scale);
    reduce_kernel<<<64, 256>>>();
    out_kernel<<<dim3(NN / (32 * OUT_TILES), BB), 256, SMEM_BYTES>>>(q, v, pe1, scale, out);
}